// round 7
// baseline (speedup 1.0000x reference)
#include <cuda_runtime.h>
#include <math.h>

#define NBATCH 2048
#define ALPHA 1e-4f
#define LN_EPS 1e-5f

#define XR_ELEMS (NBATCH*62*64)      /* 8126464 */
#define S_BASE   (XR_ELEMS + 2)

// Scratch
__device__ float g_acc[NBATCH*2790];     // [b][kf][t*62+v]
__device__ float g_twt[12288];           // [t][c][o]
__device__ float g_slhs[NBATCH*186];     // [b][v*3+s]
__device__ float g_srhs[NBATCH*186];     // [b][t*62+v]

__device__ __forceinline__ float fsig(float x){ return __fdividef(1.0f, 1.0f+__expf(-x)); }

__global__ void prep_kernel(const float* __restrict__ gtw, float* __restrict__ out) {
    int i = blockIdx.x*256 + threadIdx.x;
    if (i < 12288) {
        int o = i/192, c = (i%192)/3, t = i%3;
        g_twt[(t*64+c)*64+o] = gtw[i];
    }
    if (i < 2) out[XR_ELEMS + i] = 0.0f;
}

// ============ K1: attention chain P1-P7, 128 threads, 1 batch/block ============
__global__ void __launch_bounds__(128,12) stgcn_k1(
    const float* __restrict__ gx, const float* __restrict__ gU1,
    const float* __restrict__ gU2, const float* __restrict__ gU3,
    const float* __restrict__ gbe, const float* __restrict__ gVe,
    const float* __restrict__ gW1, const float* __restrict__ gW2,
    const float* __restrict__ gW3)
{
    extern __shared__ float smarr[];
    const int lt = threadIdx.x;
    const int b  = blockIdx.x;

    float* sx    = smarr;            // 932
    float* sxT   = sx   + 932;       // 932
    float* y_s   = sxT  + 932;       // 16
    float* lhs_s = y_s  + 16;        // 188
    float* rhs_s = lhs_s+ 188;       // 188
    float* prod_s= rhs_s+ 188;       // 12
    float* E_s   = prod_s+12;        // 12
    float* At_s  = E_s  + 12;        // 12
    float* U2_s  = At_s + 12;        // 312
    float* U1_s  = U2_s + 312;       // 64
    float* U3_s  = U1_s + 64;        // 8
    float* be_s  = U3_s + 8;         // 12
    float* Ve_s  = be_s + 12;        // 12
    float* W1_s  = Ve_s + 12;        // 4
    float* W2_s  = W1_s + 4;         // 16
    float* W3_s  = W2_s + 16;        // 8

    for (int i = lt; i < 930; i += 128) sx[i] = gx[(size_t)b*930 + i];
    for (int i = lt; i < 310; i += 128) U2_s[i] = gU2[i];
    if (lt < 62) U1_s[lt] = gU1[lt];
    else if (lt >= 64 && lt < 69)  U3_s[lt-64] = gU3[lt-64];
    else if (lt >= 70 && lt < 79)  be_s[lt-70] = gbe[lt-70];
    else if (lt >= 80 && lt < 89)  Ve_s[lt-80] = gVe[lt-80];
    else if (lt >= 90 && lt < 93)  W1_s[lt-90] = gW1[lt-90];
    else if (lt >= 96 && lt < 111) W2_s[lt-96] = gW2[lt-96];
    else if (lt >= 112 && lt < 117) W3_s[lt-112] = gW3[lt-112];
    __syncthreads();

    // P1: y + rhs
    if (lt < 15) {
        int t = lt/5, f = lt%5;
        float s = 0.f;
        for (int v = 0; v < 62; v++) s += sx[t*310+v*5+f]*U1_s[v];
        y_s[t*5+f] = s;
    }
    for (int i = lt; i < 186; i += 128) {
        int v = i/3, t = i%3;
        const float* xr = sx + t*310 + v*5;
        float s = 0.f;
        #pragma unroll
        for (int f=0; f<5; f++) s += U3_s[f]*xr[f];
        rhs_s[v*3+t] = s;
    }
    __syncthreads();
    // P2: lhs
    for (int i = lt; i < 186; i += 128) {
        int t = i/62, u = i%62;
        float s = 0.f;
        #pragma unroll
        for (int f=0; f<5; f++) s += y_s[t*5+f]*U2_s[f*62+u];
        lhs_s[t*62+u] = s;
    }
    __syncthreads();
    // P3: prod
    if (lt < 9) {
        int t = lt/3, u = lt%3;
        float s = 0.f;
        for (int v=0; v<62; v++) s += lhs_s[t*62+v]*rhs_s[v*3+u];
        prod_s[t*3+u] = s;
    }
    __syncthreads();
    // P4: E
    if (lt < 9) {
        int t = lt/3, u = lt%3;
        float s = 0.f;
        #pragma unroll
        for (int k=0; k<3; k++) s += Ve_s[t*3+k]*fsig(prod_s[k*3+u]+be_s[k*3+u]);
        E_s[t*3+u] = s;
    }
    __syncthreads();
    // P5: softmax over t
    if (lt < 3) {
        int u = lt;
        float m = fmaxf(E_s[u], fmaxf(E_s[3+u], E_s[6+u]));
        float e0=__expf(E_s[u]-m), e1=__expf(E_s[3+u]-m), e2=__expf(E_s[6+u]-m);
        float inv = __fdividef(1.0f, e0+e1+e2);
        At_s[u]=e0*inv; At_s[3+u]=e1*inv; At_s[6+u]=e2*inv;
    }
    __syncthreads();
    // P6: x_TAt
    for (int i = lt; i < 930; i += 128) {
        int u = i/310, r = i%310;
        sxT[i] = (sx[r]*At_s[u] + sx[310+r]*At_s[3+u] + sx[620+r]*At_s[6+u]) * 0.056796183f;
    }
    __syncthreads();
    // P7: slhs + srhs -> global
    for (int i = lt; i < 186; i += 128) {
        int v = i/3, s = i%3;
        float acc = 0.f;
        #pragma unroll
        for (int f=0; f<5; f++) {
            float yv = sxT[v*5+f]*W1_s[0] + sxT[310+v*5+f]*W1_s[1] + sxT[620+v*5+f]*W1_s[2];
            acc += yv*W2_s[f*3+s];
        }
        g_slhs[(size_t)b*186 + v*3+s] = acc;
        int t = i/62, vv = i%62;
        const float* xr = sxT + t*310 + vv*5;
        float s2 = 0.f;
        #pragma unroll
        for (int f=0; f<5; f++) s2 += W3_s[f]*xr[f];
        g_srhs[(size_t)b*186 + t*62+vv] = s2;
    }
}

// ============ K2: P8-P16, 256 threads, 1 batch/block, 6 blocks/SM ============
__global__ void __launch_bounds__(256,6) stgcn_k2(
    const float* __restrict__ gx, const float* __restrict__ gbs,
    const float* __restrict__ gVs, const float* __restrict__ ga,
    float* __restrict__ out)
{
    extern __shared__ float smarr[];
    const int lt = threadIdx.x;
    const int b  = blockIdx.x;

    float* sx    = smarr;            // 932
    float* bufA  = sx   + 932;       // 3968 : sigmoid [w][v]@64 then tmpS/S @62
    float* bufAt = bufA + 3968;      // 3844
    float* slhs_s= bufAt+ 3844;      // 188
    float* srhs_s= slhs_s+188;       // 188
    float* colsum= srhs_s+188;       // 64
    float* DgS_s = colsum+ 64;       // 64
    float* d2s_s = DgS_s + 64;       // 64
    float* red_s = d2s_s + 64;       // 8
    float* a_s   = red_s + 8;        // 8

    for (int i = lt; i < 930; i += 256) sx[i] = gx[(size_t)b*930 + i];
    if (lt < 186) {
        slhs_s[lt] = g_slhs[(size_t)b*186 + lt];
        srhs_s[lt] = g_srhs[(size_t)b*186 + lt];
    }
    else if (lt >= 192 && lt < 197) a_s[lt-192] = ga[lt-192];
    __syncthreads();

    // P8: sigmoid map [w][v] stride 64
    for (int i = lt; i < 3844; i += 256) {
        int w = i/62, v = i%62;
        float p = slhs_s[w*3]*srhs_s[v] + slhs_s[w*3+1]*srhs_s[62+v]
                + slhs_s[w*3+2]*srhs_s[124+v] + gbs[i];
        bufA[w*64+v] = fsig(p);
    }
    if (lt < 62) { bufA[lt*64+62]=0.f; bufA[lt*64+63]=0.f; }
    __syncthreads();
    // P9: Sm matmul (2u x 8v tile), Vs from L1/global
    {
        int u2 = lt>>3;             // 0..31
        int vq = lt&7;              // 0..7
        int u0 = u2*2;
        if (u0 < 62) {
            float acc[16];
            #pragma unroll
            for (int k=0;k<16;k++) acc[k]=0.f;
            const float* va_p = gVs + u0*62;
            const float* vb_p = va_p + 62;
            for (int w=0; w<62; w++) {
                float va = __ldg(va_p + w);
                float vb = __ldg(vb_p + w);
                const float4* rowp = reinterpret_cast<const float4*>(bufA + w*64 + vq*8);
                float4 s0 = rowp[0], s1 = rowp[1];
                float sv[8] = {s0.x,s0.y,s0.z,s0.w,s1.x,s1.y,s1.z,s1.w};
                #pragma unroll
                for (int j=0;j<8;j++) { acc[j] += va*sv[j]; acc[8+j] += vb*sv[j]; }
            }
            #pragma unroll
            for (int j=0;j<8;j++) {
                int v = vq*8+j;
                if (v < 62) {
                    bufAt[u0*62+v]     = acc[j];
                    bufAt[(u0+1)*62+v] = acc[8+j];
                }
            }
        }
    }
    __syncthreads();
    // P10: softmax over u per column v (4 lanes/col)
    {
        int v = lt>>2, g = lt&3;
        bool act = (v < 62);
        float m = -1e30f;
        if (act) for (int u=g; u<62; u+=4) m = fmaxf(m, bufAt[u*62+v]);
        m = fmaxf(m, __shfl_xor_sync(0xffffffffu, m, 1));
        m = fmaxf(m, __shfl_xor_sync(0xffffffffu, m, 2));
        float ssum = 0.f;
        if (act) for (int u=g; u<62; u+=4) { float e = __expf(bufAt[u*62+v]-m); bufAt[u*62+v]=e; ssum+=e; }
        ssum += __shfl_xor_sync(0xffffffffu, ssum, 1);
        ssum += __shfl_xor_sync(0xffffffffu, ssum, 2);
        float inv = __fdividef(1.0f, ssum);
        if (act) for (int u=g; u<62; u+=4) bufAt[u*62+v] *= inv;
    }
    __syncthreads();
    // P11: tmpS (reuse bufA, stride 62)
    const float* xm = sx + 310;
    {
        float a0=a_s[0],a1=a_s[1],a2=a_s[2],a3=a_s[3],a4=a_s[4];
        for (int i = lt; i < 3844; i += 256) {
            int ii = i/62, jj = i%62;
            const float* xi = xm + ii*5; const float* xj = xm + jj*5;
            float e = fabsf(xi[0]-xj[0])*a0 + fabsf(xi[1]-xj[1])*a1 + fabsf(xi[2]-xj[2])*a2
                    + fabsf(xi[3]-xj[3])*a3 + fabsf(xi[4]-xj[4])*a4;
            bufA[i] = __expf(fmaxf(e, 0.0f));
        }
    }
    __syncthreads();
    // P12: column reciprocal
    {
        int j = lt>>2, g = lt&3;
        bool act = (j < 62);
        float cs = 0.f;
        if (act) for (int i=g; i<62; i+=4) cs += bufA[i*62+j];
        cs += __shfl_xor_sync(0xffffffffu, cs, 1);
        cs += __shfl_xor_sync(0xffffffffu, cs, 2);
        if (act && g==0) colsum[j] = __fdividef(1.0f, cs);
    }
    __syncthreads();
    // P13: normalize + store S
    for (int i = lt; i < 3844; i += 256) {
        float s = bufA[i] * colsum[i%62];
        bufA[i] = s;
        out[S_BASE + (size_t)b*3844 + i] = s;
    }
    __syncthreads();
    // P14: Dg + d2
    {
        int j = lt>>2, g = lt&3;
        bool act = (j < 62);
        float cs = 0.f, dd = 0.f;
        if (act) {
            const float* xj = xm + j*5;
            for (int i=g; i<62; i+=4) {
                cs += bufA[i*62+j];
                const float* xi = xm + i*5;
                #pragma unroll
                for (int f=0; f<5; f++) { float d = xj[f]-xi[f]; dd += d*d; }
            }
        }
        cs += __shfl_xor_sync(0xffffffffu, cs, 1);
        cs += __shfl_xor_sync(0xffffffffu, cs, 2);
        dd += __shfl_xor_sync(0xffffffffu, dd, 1);
        dd += __shfl_xor_sync(0xffffffffu, dd, 2);
        if (act && g==0) { DgS_s[j] = cs; d2s_s[j] = dd; }
    }
    __syncthreads();
    // P15: Sloss partials
    {
        float sl = 0.f;
        for (int i = lt; i < 3844; i += 256) sl += bufA[i]*bufA[i];
        #pragma unroll
        for (int o=16; o; o>>=1) sl += __shfl_xor_sync(0xffffffffu, sl, o);
        if ((lt&31)==0) red_s[lt>>5] = sl;
    }
    __syncthreads();
    // P16: cheb accumulators + loss finalize
    if (lt < 186) {
        int t = lt/62, v = lt%62;
        float acc[15];
        #pragma unroll
        for (int k=0;k<15;k++) acc[k]=0.f;
        float dgm1 = DgS_s[v] - 1.0f;
        for (int u=0; u<62; u++) {
            float s  = bufA[u*62+v];
            float at = bufAt[u*62+v];
            float delta = (u==v) ? 1.0f : 0.0f;
            float lt_ = dgm1*delta - s;
            float c2 = 2.0f*lt_*lt_ - delta;
            float t0 = delta*at, t1 = lt_*at, t2 = c2*at;
            const float* xr = sx + t*310 + u*5;
            #pragma unroll
            for (int f=0; f<5; f++) {
                float xv = xr[f];
                acc[f]    += t0*xv;
                acc[5+f]  += t1*xv;
                acc[10+f] += t2*xv;
            }
        }
        size_t base = (size_t)b*2790 + t*62 + v;
        #pragma unroll
        for (int kf=0; kf<15; kf++) g_acc[base + kf*186] = acc[kf];
    } else if (lt == 192) {
        float sl = 0.f;
        #pragma unroll
        for (int w=0; w<8; w++) sl += red_s[w];
        atomicAdd(out + XR_ELEMS, sl * (ALPHA/(float)NBATCH));
        float dp = 0.f;
        for (int j=0; j<62; j++) dp += DgS_s[j]*d2s_s[j];
        atomicAdd(out + XR_ELEMS + 1, dp * ALPHA);
    }
}

// ============================ K3: phases 4b-6 ============================
__global__ void __launch_bounds__(512,3) stgcn_k3(
    const float* __restrict__ gx, const float* __restrict__ gTheta,
    const float* __restrict__ gtb, const float* __restrict__ grw,
    const float* __restrict__ grb, const float* __restrict__ ggamma,
    const float* __restrict__ gbeta, float* __restrict__ out)
{
    extern __shared__ float smarr[];
    const int tid = threadIdx.x;
    const int b = blockIdx.x;

    float* sg    = smarr;              // 12288 [t][c][v] rowstride 64
    float* zb    = sg   + 12288;       // 4032  z [v][o] rowstride 65
    float* Th_s  = zb   + 4032;        // 960   [kf][o]
    float* x0_s  = Th_s + 960;         // 320
    float* tb_s  = x0_s + 320;         // 64
    float* rb_s  = tb_s + 64;          // 64
    float* rw_s  = rb_s + 64;          // 320
    float* gam_s = rw_s + 320;         // 64
    float* bet_s = gam_s+ 64;          // 64
    float* mu_s  = bet_s+ 64;          // 64
    float* iv_s  = mu_s + 64;          // 64

    for (int i = tid; i < 960; i += 512) Th_s[i] = gTheta[i];
    for (int i = tid; i < 310; i += 512) x0_s[i] = gx[(size_t)b*930 + i];
    for (int i = tid; i < 320; i += 512) rw_s[i] = grw[i];
    if (tid < 64) { tb_s[tid]=gtb[tid]; rb_s[tid]=grb[tid]; gam_s[tid]=ggamma[tid]; bet_s[tid]=gbeta[tid]; }
    __syncthreads();

    // Phase 4b: Theta contraction -> sg
    if (tid < 372) {
        int oh = (tid >= 186);
        int r = tid - oh*186;
        int t = r/62, v = r%62;
        int tv = t*62+v;
        const float* ap = g_acc + (size_t)b*2790 + tv;
        float a0[15];
        #pragma unroll
        for (int kf=0; kf<15; kf++) a0[kf] = __ldg(ap + kf*186);
        int ob = oh*32;
        #pragma unroll 4
        for (int oi=0; oi<32; oi++) {
            int o = ob+oi;
            float z = 0.f;
            #pragma unroll
            for (int kf=0; kf<15; kf++) z += a0[kf]*Th_s[kf*64+o];
            sg[t*4096 + o*64 + v] = fmaxf(z, 0.0f);
        }
    }
    for (int i = tid; i < 192; i += 512) {
        int t = i/64, c = i%64;
        sg[t*4096 + c*64 + 62] = 0.f;
        sg[t*4096 + c*64 + 63] = 0.f;
    }
    __syncthreads();

    // Phase 5: temporal conv (2o x 8v, 2-way c-split)
    {
        int o2  = tid>>4;
        int rem = tid&15;
        int vq  = rem>>1;
        int ks  = rem&1;
        int o0  = o2*2;
        float acc[16];
        #pragma unroll
        for (int k=0;k<16;k++) acc[k]=0.f;
        int c0 = ks*32;
        for (int ci=0; ci<32; ci++) {
            int c = c0+ci;
            #pragma unroll
            for (int t=0; t<3; t++) {
                const float4* rowp = reinterpret_cast<const float4*>(sg + t*4096 + c*64 + vq*8);
                float4 s0 = rowp[0], s1 = rowp[1];
                float2 tw2 = __ldg(reinterpret_cast<const float2*>(g_twt + ((t*64+c)<<6) + o0));
                float sv[8] = {s0.x,s0.y,s0.z,s0.w,s1.x,s1.y,s1.z,s1.w};
                #pragma unroll
                for (int vj=0; vj<8; vj++) {
                    acc[vj]   += tw2.x*sv[vj];
                    acc[8+vj] += tw2.y*sv[vj];
                }
            }
        }
        #pragma unroll
        for (int k=0;k<16;k++) acc[k] += __shfl_xor_sync(0xffffffffu, acc[k], 1);
        #pragma unroll
        for (int dv=0; dv<4; dv++) {
            int vj = ks*4+dv;
            int v = vq*8+vj;
            if (v < 62) {
                const float* x0 = x0_s + v*5;
                float xa=x0[0], xb=x0[1], xc=x0[2], xd=x0[3], xe=x0[4];
                #pragma unroll
                for (int oi=0; oi<2; oi++) {
                    int o = o0+oi;
                    float tcv = (acc[oi*8+vj] + tb_s[o]) * 0.25819889f;
                    const float* rwp = rw_s + o*5;
                    float resv = rb_s[o] + xa*rwp[0]+xb*rwp[1]+xc*rwp[2]+xd*rwp[3]+xe*rwp[4];
                    zb[v*65+o] = fmaxf(resv + tcv, 0.0f);
                }
            }
        }
    }
    __syncthreads();

    // Phase 6: LayerNorm + writeback
    {
        int v = tid>>3, g = tid&7;
        bool act = (v < 62);
        float s = 0.f;
        if (act) for (int o=g; o<64; o+=8) s += zb[v*65+o];
        #pragma unroll
        for (int o=4; o; o>>=1) s += __shfl_xor_sync(0xffffffffu, s, o);
        float mu = s * (1.0f/64.0f);
        float vv = 0.f;
        if (act) for (int o=g; o<64; o+=8) { float d = zb[v*65+o]-mu; vv += d*d; }
        #pragma unroll
        for (int o=4; o; o>>=1) vv += __shfl_xor_sync(0xffffffffu, vv, o);
        vv *= (1.0f/64.0f);
        if (act && g==0) { mu_s[v] = mu; iv_s[v] = rsqrtf(vv + LN_EPS); }
    }
    __syncthreads();
    for (int i = tid; i < 3968; i += 512) {
        int v = i>>6, o = i&63;
        float val = (zb[v*65+o]-mu_s[v])*iv_s[v]*gam_s[o] + bet_s[o];
        out[(size_t)b*3968 + i] = val;
    }
}

#define SMEM_K1_BYTES (2728*4)
#define SMEM_K2_BYTES (9328*4)
#define SMEM_K3_BYTES (18304*4)

extern "C" void kernel_launch(void* const* d_in, const int* in_sizes, int n_in,
                              void* d_out, int out_size) {
    const float* x     = (const float*)d_in[0];
    const float* U1    = (const float*)d_in[1];
    const float* U2    = (const float*)d_in[2];
    const float* U3    = (const float*)d_in[3];
    const float* be    = (const float*)d_in[4];
    const float* Ve    = (const float*)d_in[5];
    const float* W1    = (const float*)d_in[6];
    const float* W2    = (const float*)d_in[7];
    const float* W3    = (const float*)d_in[8];
    const float* bs    = (const float*)d_in[9];
    const float* Vs    = (const float*)d_in[10];
    const float* a     = (const float*)d_in[11];
    const float* Theta = (const float*)d_in[12];
    const float* tw    = (const float*)d_in[13];
    const float* tb    = (const float*)d_in[14];
    const float* rw    = (const float*)d_in[15];
    const float* rb    = (const float*)d_in[16];
    const float* gamma = (const float*)d_in[17];
    const float* beta  = (const float*)d_in[18];
    float* out = (float*)d_out;

    cudaFuncSetAttribute(stgcn_k1, cudaFuncAttributeMaxDynamicSharedMemorySize, SMEM_K1_BYTES);
    cudaFuncSetAttribute(stgcn_k2, cudaFuncAttributeMaxDynamicSharedMemorySize, SMEM_K2_BYTES);
    cudaFuncSetAttribute(stgcn_k3, cudaFuncAttributeMaxDynamicSharedMemorySize, SMEM_K3_BYTES);

    prep_kernel<<<48, 256>>>(tw, out);
    stgcn_k1<<<NBATCH, 128, SMEM_K1_BYTES>>>(x, U1, U2, U3, be, Ve, W1, W2, W3);
    stgcn_k2<<<NBATCH, 256, SMEM_K2_BYTES>>>(x, bs, Vs, a, out);
    stgcn_k3<<<NBATCH, 512, SMEM_K3_BYTES>>>(x, Theta, tb, rw, rb, gamma, beta, out);
}

// round 8
// speedup vs baseline: 1.1302x; 1.1302x over previous
#include <cuda_runtime.h>
#include <math.h>

#define NBATCH 2048
#define ALPHA 1e-4f
#define LN_EPS 1e-5f

#define XR_ELEMS (NBATCH*62*64)      /* 8126464 */
#define S_BASE   (XR_ELEMS + 2)

// Scratch: per-batch cheb accumulators [b][tv][16] (kf-contig, padded), transposed tw.
__device__ float g_acc[NBATCH*2976];
__device__ float g_twt[12288];           // [t][c][o]

__device__ __forceinline__ float fsig(float x){ return __fdividef(1.0f, 1.0f+__expf(-x)); }

__global__ void prep_kernel(const float* __restrict__ gtw, float* __restrict__ out) {
    int i = blockIdx.x*256 + threadIdx.x;
    if (i < 12288) {
        int o = i/192, c = (i%192)/3, t = i%3;
        g_twt[(t*64+c)*64+o] = gtw[i];
    }
    if (i < 2) out[XR_ELEMS + i] = 0.0f;
}

// ============ KERNEL A: phases 0-4a, 256 threads, 1 batch/block ============
__global__ void __launch_bounds__(256,5) stgcn_a(
    const float* __restrict__ gx, const float* __restrict__ gU1,
    const float* __restrict__ gU2, const float* __restrict__ gU3,
    const float* __restrict__ gbe, const float* __restrict__ gVe,
    const float* __restrict__ gW1, const float* __restrict__ gW2,
    const float* __restrict__ gW3, const float* __restrict__ gbs,
    const float* __restrict__ gVs, const float* __restrict__ ga,
    float* __restrict__ out)
{
    extern __shared__ float smarr[];
    const int lt = threadIdx.x;
    const int b  = blockIdx.x;

    float* sx    = smarr;            // 932
    float* sxT   = sx   + 932;       // 932
    float* bufA  = sxT  + 932;       // 3968
    float* bufAt = bufA + 3968;      // 3844
    float* y_s   = bufAt+ 3844;      // 16
    float* lhs_s = y_s  + 16;        // 188
    float* rhs_s = lhs_s+ 188;       // 188
    float* prod_s= rhs_s+ 188;       // 12
    float* E_s   = prod_s+12;        // 12
    float* At_s  = E_s  + 12;        // 12
    float* slhs_s= At_s + 12;        // 188
    float* srhs_s= slhs_s+188;       // 188
    float* colsum= srhs_s+188;       // 64
    float* DgS_s = colsum+ 64;       // 64
    float* d2s_s = DgS_s + 64;       // 64
    float* red_s = d2s_s + 64;       // 8
    float* U2_s  = red_s + 8;        // 312
    float* U1_s  = U2_s + 312;       // 64
    float* U3_s  = U1_s + 64;        // 8
    float* be_s  = U3_s + 8;         // 12
    float* Ve_s  = be_s + 12;        // 12
    float* W1_s  = Ve_s + 12;        // 4
    float* W2_s  = W1_s + 4;         // 16
    float* W3_s  = W2_s + 16;        // 8
    float* a_s   = W3_s + 8;         // 8

    for (int i = lt; i < 930; i += 256) sx[i] = gx[(size_t)b*930 + i];
    if (lt >= 128 && lt < 128+155) {
        U2_s[(lt-128)*2]   = gU2[(lt-128)*2];
        U2_s[(lt-128)*2+1] = gU2[(lt-128)*2+1];
    }
    if (lt < 62) U1_s[lt] = gU1[lt];
    else if (lt >= 64 && lt < 69)  U3_s[lt-64] = gU3[lt-64];
    else if (lt >= 70 && lt < 79)  be_s[lt-70] = gbe[lt-70];
    else if (lt >= 80 && lt < 89)  Ve_s[lt-80] = gVe[lt-80];
    else if (lt >= 90 && lt < 93)  W1_s[lt-90] = gW1[lt-90];
    else if (lt >= 96 && lt < 111) W2_s[lt-96] = gW2[lt-96];
    else if (lt >= 112 && lt < 117) W3_s[lt-112] = gW3[lt-112];
    else if (lt >= 118 && lt < 123) a_s[lt-118] = ga[lt-118];
    __syncthreads();

    // P1: y + rhs
    if (lt < 15) {
        int t = lt/5, f = lt%5;
        float s = 0.f;
        for (int v = 0; v < 62; v++) s += sx[t*310+v*5+f]*U1_s[v];
        y_s[t*5+f] = s;
    }
    if (lt >= 32 && lt < 218) {
        int r = lt-32;
        int v = r/3, t = r%3;
        const float* xr = sx + t*310 + v*5;
        float s = 0.f;
        #pragma unroll
        for (int f=0; f<5; f++) s += U3_s[f]*xr[f];
        rhs_s[v*3+t] = s;
    }
    __syncthreads();
    // P2: lhs
    if (lt < 186) {
        int t = lt/62, u = lt%62;
        float s = 0.f;
        #pragma unroll
        for (int f=0; f<5; f++) s += y_s[t*5+f]*U2_s[f*62+u];
        lhs_s[t*62+u] = s;
    }
    __syncthreads();
    // P3: prod
    if (lt < 9) {
        int t = lt/3, u = lt%3;
        float s = 0.f;
        for (int v=0; v<62; v++) s += lhs_s[t*62+v]*rhs_s[v*3+u];
        prod_s[t*3+u] = s;
    }
    __syncthreads();
    // P4: E
    if (lt < 9) {
        int t = lt/3, u = lt%3;
        float s = 0.f;
        #pragma unroll
        for (int k=0; k<3; k++) s += Ve_s[t*3+k]*fsig(prod_s[k*3+u]+be_s[k*3+u]);
        E_s[t*3+u] = s;
    }
    __syncthreads();
    // P5: softmax over t
    if (lt < 3) {
        int u = lt;
        float m = fmaxf(E_s[u], fmaxf(E_s[3+u], E_s[6+u]));
        float e0=__expf(E_s[u]-m), e1=__expf(E_s[3+u]-m), e2=__expf(E_s[6+u]-m);
        float inv = __fdividef(1.0f, e0+e1+e2);
        At_s[u]=e0*inv; At_s[3+u]=e1*inv; At_s[6+u]=e2*inv;
    }
    __syncthreads();
    // P6: x_TAt
    for (int i = lt; i < 930; i += 256) {
        int u = i/310, r = i%310;
        sxT[i] = (sx[r]*At_s[u] + sx[310+r]*At_s[3+u] + sx[620+r]*At_s[6+u]) * 0.056796183f;
    }
    __syncthreads();
    // P7: slhs + srhs
    if (lt < 186) {
        int v = lt/3, s = lt%3;
        float acc = 0.f;
        #pragma unroll
        for (int f=0; f<5; f++) {
            float yv = sxT[v*5+f]*W1_s[0] + sxT[310+v*5+f]*W1_s[1] + sxT[620+v*5+f]*W1_s[2];
            acc += yv*W2_s[f*3+s];
        }
        slhs_s[v*3+s] = acc;
        int t = lt/62, vv = lt%62;
        const float* xr = sxT + t*310 + vv*5;
        float s2 = 0.f;
        #pragma unroll
        for (int f=0; f<5; f++) s2 += W3_s[f]*xr[f];
        srhs_s[t*62+vv] = s2;
    }
    __syncthreads();
    // P8: sigmoid map [w][v] stride 64
    for (int i = lt; i < 3844; i += 256) {
        int w = i/62, v = i%62;
        float p = slhs_s[w*3]*srhs_s[v] + slhs_s[w*3+1]*srhs_s[62+v]
                + slhs_s[w*3+2]*srhs_s[124+v] + gbs[i];
        bufA[w*64+v] = fsig(p);
    }
    if (lt < 62) { bufA[lt*64+62]=0.f; bufA[lt*64+63]=0.f; }
    __syncthreads();
    // P9: Sm matmul (2u x 8v tile), Vs via L1
    {
        int u2 = lt>>3;
        int vq = lt&7;
        int u0 = u2*2;
        if (u0 < 62) {
            float acc[16];
            #pragma unroll
            for (int k=0;k<16;k++) acc[k]=0.f;
            const float* va_p = gVs + u0*62;
            const float* vb_p = va_p + 62;
            for (int w=0; w<62; w++) {
                float va = __ldg(va_p + w);
                float vb = __ldg(vb_p + w);
                const float4* rowp = reinterpret_cast<const float4*>(bufA + w*64 + vq*8);
                float4 s0 = rowp[0], s1 = rowp[1];
                float sv[8] = {s0.x,s0.y,s0.z,s0.w,s1.x,s1.y,s1.z,s1.w};
                #pragma unroll
                for (int j=0;j<8;j++) { acc[j] += va*sv[j]; acc[8+j] += vb*sv[j]; }
            }
            #pragma unroll
            for (int j=0;j<8;j++) {
                int v = vq*8+j;
                if (v < 62) {
                    bufAt[u0*62+v]     = acc[j];
                    bufAt[(u0+1)*62+v] = acc[8+j];
                }
            }
        }
    }
    __syncthreads();
    // P10: softmax over u per column v (4 lanes/col)
    {
        int v = lt>>2, g = lt&3;
        bool act = (v < 62);
        float m = -1e30f;
        if (act) for (int u=g; u<62; u+=4) m = fmaxf(m, bufAt[u*62+v]);
        m = fmaxf(m, __shfl_xor_sync(0xffffffffu, m, 1));
        m = fmaxf(m, __shfl_xor_sync(0xffffffffu, m, 2));
        float ssum = 0.f;
        if (act) for (int u=g; u<62; u+=4) { float e = __expf(bufAt[u*62+v]-m); bufAt[u*62+v]=e; ssum+=e; }
        ssum += __shfl_xor_sync(0xffffffffu, ssum, 1);
        ssum += __shfl_xor_sync(0xffffffffu, ssum, 2);
        float inv = __fdividef(1.0f, ssum);
        if (act) for (int u=g; u<62; u+=4) bufAt[u*62+v] *= inv;
    }
    __syncthreads();
    // P11: tmpS (reuse bufA, stride 62)
    const float* xm = sx + 310;
    {
        float a0=a_s[0],a1=a_s[1],a2=a_s[2],a3=a_s[3],a4=a_s[4];
        for (int i = lt; i < 3844; i += 256) {
            int ii = i/62, jj = i%62;
            const float* xi = xm + ii*5; const float* xj = xm + jj*5;
            float e = fabsf(xi[0]-xj[0])*a0 + fabsf(xi[1]-xj[1])*a1 + fabsf(xi[2]-xj[2])*a2
                    + fabsf(xi[3]-xj[3])*a3 + fabsf(xi[4]-xj[4])*a4;
            bufA[i] = __expf(fmaxf(e, 0.0f));
        }
    }
    __syncthreads();
    // P12: column reciprocal
    {
        int j = lt>>2, g = lt&3;
        bool act = (j < 62);
        float cs = 0.f;
        if (act) for (int i=g; i<62; i+=4) cs += bufA[i*62+j];
        cs += __shfl_xor_sync(0xffffffffu, cs, 1);
        cs += __shfl_xor_sync(0xffffffffu, cs, 2);
        if (act && g==0) colsum[j] = __fdividef(1.0f, cs);
    }
    __syncthreads();
    // P13: normalize + store S
    for (int i = lt; i < 3844; i += 256) {
        float s = bufA[i] * colsum[i%62];
        bufA[i] = s;
        out[S_BASE + (size_t)b*3844 + i] = s;
    }
    __syncthreads();
    // P14: Dg + d2
    {
        int j = lt>>2, g = lt&3;
        bool act = (j < 62);
        float cs = 0.f, dd = 0.f;
        if (act) {
            const float* xj = xm + j*5;
            for (int i=g; i<62; i+=4) {
                cs += bufA[i*62+j];
                const float* xi = xm + i*5;
                #pragma unroll
                for (int f=0; f<5; f++) { float d = xj[f]-xi[f]; dd += d*d; }
            }
        }
        cs += __shfl_xor_sync(0xffffffffu, cs, 1);
        cs += __shfl_xor_sync(0xffffffffu, cs, 2);
        dd += __shfl_xor_sync(0xffffffffu, dd, 1);
        dd += __shfl_xor_sync(0xffffffffu, dd, 2);
        if (act && g==0) { DgS_s[j] = cs; d2s_s[j] = dd; }
    }
    __syncthreads();
    // P15: Sloss partials
    {
        float sl = 0.f;
        for (int i = lt; i < 3844; i += 256) sl += bufA[i]*bufA[i];
        #pragma unroll
        for (int o=16; o; o>>=1) sl += __shfl_xor_sync(0xffffffffu, sl, o);
        if ((lt&31)==0) red_s[lt>>5] = sl;
    }
    __syncthreads();
    // P16: cheb accumulators -> g_acc [b][tv][16] + loss finalize
    if (lt < 186) {
        int t = lt/62, v = lt%62;
        float acc[15];
        #pragma unroll
        for (int k=0;k<15;k++) acc[k]=0.f;
        float dgm1 = DgS_s[v] - 1.0f;
        for (int u=0; u<62; u++) {
            float s  = bufA[u*62+v];
            float at = bufAt[u*62+v];
            float delta = (u==v) ? 1.0f : 0.0f;
            float lt_ = dgm1*delta - s;
            float c2 = 2.0f*lt_*lt_ - delta;
            float t0 = delta*at, t1 = lt_*at, t2 = c2*at;
            const float* xr = sx + t*310 + u*5;
            #pragma unroll
            for (int f=0; f<5; f++) {
                float xv = xr[f];
                acc[f]    += t0*xv;
                acc[5+f]  += t1*xv;
                acc[10+f] += t2*xv;
            }
        }
        float4* gp = reinterpret_cast<float4*>(g_acc + (size_t)b*2976 + (size_t)(t*62+v)*16);
        gp[0] = make_float4(acc[0],acc[1],acc[2],acc[3]);
        gp[1] = make_float4(acc[4],acc[5],acc[6],acc[7]);
        gp[2] = make_float4(acc[8],acc[9],acc[10],acc[11]);
        gp[3] = make_float4(acc[12],acc[13],acc[14],0.0f);
    } else if (lt == 192) {
        float sl = 0.f;
        #pragma unroll
        for (int w=0; w<8; w++) sl += red_s[w];
        atomicAdd(out + XR_ELEMS, sl * (ALPHA/(float)NBATCH));
        float dp = 0.f;
        for (int j=0; j<62; j++) dp += DgS_s[j]*d2s_s[j];
        atomicAdd(out + XR_ELEMS + 1, dp * ALPHA);
    }
}

// ============ K3: phases 4b-6, crossbar-light ============
__global__ void __launch_bounds__(512,3) stgcn_k3(
    const float* __restrict__ gx, const float* __restrict__ gTheta,
    const float* __restrict__ gtb, const float* __restrict__ grw,
    const float* __restrict__ grb, const float* __restrict__ ggamma,
    const float* __restrict__ gbeta, float* __restrict__ out)
{
    extern __shared__ float smarr[];
    const int tid = threadIdx.x;
    const int b = blockIdx.x;

    float* sg    = smarr;              // 12288 [t][c][v] rowstride 64
    float* zb    = sg   + 12288;       // 4032  z [v][o] rowstride 65
    float* Th_s  = zb   + 4032;        // 960   [kf][o]
    float* x0_s  = Th_s + 960;         // 320
    float* tb_s  = x0_s + 320;         // 64
    float* rb_s  = tb_s + 64;          // 64
    float* rw_s  = rb_s + 64;          // 320
    float* gam_s = rw_s + 320;         // 64
    float* bet_s = gam_s+ 64;          // 64
    float* mu_s  = bet_s+ 64;          // 64
    float* iv_s  = mu_s + 64;          // 64

    for (int i = tid; i < 960; i += 512) Th_s[i] = gTheta[i];
    for (int i = tid; i < 310; i += 512) x0_s[i] = gx[(size_t)b*930 + i];
    for (int i = tid; i < 320; i += 512) rw_s[i] = grw[i];
    if (tid < 64) { tb_s[tid]=gtb[tid]; rb_s[tid]=grb[tid]; gam_s[tid]=ggamma[tid]; bet_s[tid]=gbeta[tid]; }
    __syncthreads();

    // Phase 4b: Theta contraction -> sg (float4 Th loads)
    if (tid < 372) {
        int oh = (tid >= 186);
        int r = tid - oh*186;
        int t = r/62, v = r%62;
        int tv = t*62+v;
        const float4* ap4 = reinterpret_cast<const float4*>(g_acc + (size_t)b*2976 + (size_t)tv*16);
        float4 A0=__ldg(ap4), A1=__ldg(ap4+1), A2=__ldg(ap4+2), A3=__ldg(ap4+3);
        float a0[15] = {A0.x,A0.y,A0.z,A0.w, A1.x,A1.y,A1.z,A1.w,
                        A2.x,A2.y,A2.z,A2.w, A3.x,A3.y,A3.z};
        const float4* Th4 = reinterpret_cast<const float4*>(Th_s);  // [kf][16]
        int qb = oh*8;
        float* sgr = sg + t*4096 + v;
        #pragma unroll 2
        for (int q=0; q<8; q++) {
            int oq = qb+q;
            float zx=0.f, zy=0.f, zz=0.f, zw=0.f;
            #pragma unroll
            for (int kf=0; kf<15; kf++) {
                float4 th = Th4[kf*16+oq];
                float av = a0[kf];
                zx += av*th.x; zy += av*th.y; zz += av*th.z; zw += av*th.w;
            }
            int o0 = oq*4;
            sgr[(o0  )*64] = fmaxf(zx, 0.0f);
            sgr[(o0+1)*64] = fmaxf(zy, 0.0f);
            sgr[(o0+2)*64] = fmaxf(zz, 0.0f);
            sgr[(o0+3)*64] = fmaxf(zw, 0.0f);
        }
    }
    for (int i = tid; i < 192; i += 512) {
        int t = i/64, c = i%64;
        sg[t*4096 + c*64 + 62] = 0.f;
        sg[t*4096 + c*64 + 63] = 0.f;
    }
    __syncthreads();

    // Phase 5: temporal conv — 8o x 2v per thread, 2-way k-split, tw via L1
    {
        int og  = tid & 7;            // o-group: o = og*8..+8
        int kh  = (tid >> 3) & 1;     // k-half
        int vgl = (tid >> 4) & 1;
        int w   = tid >> 5;           // warp
        int vg  = w*2 + vgl;          // 0..31
        int o0  = og*8;
        int v0  = vg*2;
        float acc[16];                // [vj*8+oi]
        #pragma unroll
        for (int k=0;k<16;k++) acc[k]=0.f;
        int tc0 = kh*96;
        #pragma unroll 2
        for (int tc = tc0; tc < tc0+96; tc++) {
            int t = tc>>6, c = tc&63;
            float2 sv = *reinterpret_cast<const float2*>(sg + t*4096 + c*64 + v0);
            const float4* twp = reinterpret_cast<const float4*>(g_twt + (t<<12) + (c<<6) + o0);
            float4 w0 = __ldg(twp), w1 = __ldg(twp+1);
            acc[0]  += sv.x*w0.x; acc[1]  += sv.x*w0.y; acc[2]  += sv.x*w0.z; acc[3]  += sv.x*w0.w;
            acc[4]  += sv.x*w1.x; acc[5]  += sv.x*w1.y; acc[6]  += sv.x*w1.z; acc[7]  += sv.x*w1.w;
            acc[8]  += sv.y*w0.x; acc[9]  += sv.y*w0.y; acc[10] += sv.y*w0.z; acc[11] += sv.y*w0.w;
            acc[12] += sv.y*w1.x; acc[13] += sv.y*w1.y; acc[14] += sv.y*w1.z; acc[15] += sv.y*w1.w;
        }
        #pragma unroll
        for (int k=0;k<16;k++) acc[k] += __shfl_xor_sync(0xffffffffu, acc[k], 8);
        if (kh == 0 && v0 < 62) {
            #pragma unroll
            for (int vj=0; vj<2; vj++) {
                int v = v0+vj;
                if (v < 62) {
                    const float* x0 = x0_s + v*5;
                    float xa=x0[0], xb=x0[1], xc=x0[2], xd=x0[3], xe=x0[4];
                    #pragma unroll
                    for (int oi=0; oi<8; oi++) {
                        int o = o0+oi;
                        float tcv = (acc[vj*8+oi] + tb_s[o]) * 0.25819889f;
                        const float* rwp = rw_s + o*5;
                        float resv = rb_s[o] + xa*rwp[0]+xb*rwp[1]+xc*rwp[2]+xd*rwp[3]+xe*rwp[4];
                        zb[v*65+o] = fmaxf(resv + tcv, 0.0f);
                    }
                }
            }
        }
    }
    __syncthreads();

    // Phase 6: LayerNorm + writeback
    {
        int v = tid>>3, g = tid&7;
        bool act = (v < 62);
        float s = 0.f;
        if (act) for (int o=g; o<64; o+=8) s += zb[v*65+o];
        #pragma unroll
        for (int o=4; o; o>>=1) s += __shfl_xor_sync(0xffffffffu, s, o);
        float mu = s * (1.0f/64.0f);
        float vv = 0.f;
        if (act) for (int o=g; o<64; o+=8) { float d = zb[v*65+o]-mu; vv += d*d; }
        #pragma unroll
        for (int o=4; o; o>>=1) vv += __shfl_xor_sync(0xffffffffu, vv, o);
        vv *= (1.0f/64.0f);
        if (act && g==0) { mu_s[v] = mu; iv_s[v] = rsqrtf(vv + LN_EPS); }
    }
    __syncthreads();
    for (int i = tid; i < 3968; i += 512) {
        int v = i>>6, o = i&63;
        float val = (zb[v*65+o]-mu_s[v])*iv_s[v]*gam_s[o] + bet_s[o];
        out[(size_t)b*3968 + i] = val;
    }
}

#define SMEM_A_BYTES (11124*4)
#define SMEM_K3_BYTES (18304*4)

extern "C" void kernel_launch(void* const* d_in, const int* in_sizes, int n_in,
                              void* d_out, int out_size) {
    const float* x     = (const float*)d_in[0];
    const float* U1    = (const float*)d_in[1];
    const float* U2    = (const float*)d_in[2];
    const float* U3    = (const float*)d_in[3];
    const float* be    = (const float*)d_in[4];
    const float* Ve    = (const float*)d_in[5];
    const float* W1    = (const float*)d_in[6];
    const float* W2    = (const float*)d_in[7];
    const float* W3    = (const float*)d_in[8];
    const float* bs    = (const float*)d_in[9];
    const float* Vs    = (const float*)d_in[10];
    const float* a     = (const float*)d_in[11];
    const float* Theta = (const float*)d_in[12];
    const float* tw    = (const float*)d_in[13];
    const float* tb    = (const float*)d_in[14];
    const float* rw    = (const float*)d_in[15];
    const float* rb    = (const float*)d_in[16];
    const float* gamma = (const float*)d_in[17];
    const float* beta  = (const float*)d_in[18];
    float* out = (float*)d_out;

    cudaFuncSetAttribute(stgcn_a, cudaFuncAttributeMaxDynamicSharedMemorySize, SMEM_A_BYTES);
    cudaFuncSetAttribute(stgcn_k3, cudaFuncAttributeMaxDynamicSharedMemorySize, SMEM_K3_BYTES);

    prep_kernel<<<48, 256>>>(tw, out);
    stgcn_a<<<NBATCH, 256, SMEM_A_BYTES>>>(x, U1, U2, U3, be, Ve, W1, W2, W3,
                                           bs, Vs, a, out);
    stgcn_k3<<<NBATCH, 512, SMEM_K3_BYTES>>>(x, Theta, tb, rw, rb, gamma, beta, out);
}